// round 1
// baseline (speedup 1.0000x reference)
#include <cuda_runtime.h>
#include <cuda_bf16.h>
#include <math.h>
#include <stdint.h>

// Problem constants
#define NB   128          // batch
#define TT   32           // timesteps used (T-1)
#define NTOK (128*33)     // caption elements
#define DF   1280
#define WD   256
#define HH   512
#define VV   32000
#define M_NT (NB*TT)      // 4096 rows (n*32+t)
#define G4   (4*HH)       // 2048
#define NTILES_V (VV/64)  // 500

// ---------------- device scratch (no allocs allowed) ----------------
__device__ float g_XWx[M_NT * G4];        // x@Wx + b, all timesteps (33.5 MB)
__device__ float g_h_all[M_NT * HH];      // h for every (n,t) (8.4 MB)
__device__ float g_h[NB * HH];
__device__ float g_c[NB * HH];
__device__ float g_A[NB * G4];            // per-step gate pre-activations
__device__ float g_part[(size_t)M_NT * NTILES_V]; // per-(row, ntile) sumexp partials
__device__ float g_tsc[M_NT];
__device__ float g_nll[M_NT];
__device__ int   g_rows[M_NT];            // captions_in flattened
__device__ int   g_tgt[M_NT];             // captions_out flattened
__device__ int   g_is64;

// ---------------- caption dtype detection ----------------
__global__ void detect_kernel(const unsigned int* __restrict__ w) {
    __shared__ int found;
    if (threadIdx.x == 0) found = 0;
    __syncthreads();
    // If captions are int64 (values < 32000), every odd 32-bit word is 0.
    for (int i = threadIdx.x; i < NTOK / 2; i += blockDim.x)
        if (w[2 * i + 1] != 0u) found = 1;
    __syncthreads();
    if (threadIdx.x == 0) g_is64 = (found == 0) ? 1 : 0;
}

__global__ void build_idx_kernel(const void* __restrict__ caps) {
    int m = blockIdx.x * blockDim.x + threadIdx.x;
    if (m >= M_NT) return;
    int n = m >> 5, t = m & 31;
    int ci, co;
    if (g_is64) {
        const long long* c = (const long long*)caps;
        ci = (int)c[n * 33 + t];
        co = (int)c[n * 33 + t + 1];
    } else {
        const int* c = (const int*)caps;
        ci = c[n * 33 + t];
        co = c[n * 33 + t + 1];
    }
    g_rows[m] = ci;
    g_tgt[m]  = co;
}

// ---------------- generic tiled SGEMM ----------------
// C[m,n] = sum_k A[rowidx?rowidx[m]:m, k] * B[k,n] (+bias[n]) (+add[m*ldadd+n])
template<int BM, int BN, int BK, int TM, int TN>
__global__ void __launch_bounds__(256)
sgemm_k(const float* __restrict__ A, int lda,
        const float* __restrict__ B, int ldb,
        float* __restrict__ C, int ldc,
        const float* __restrict__ bias,
        const float* __restrict__ add, int ldadd,
        const int* __restrict__ rowidx,
        int K)
{
    constexpr int THREADS = (BM / TM) * (BN / TN);
    constexpr int ALOAD = BM * BK / THREADS;
    constexpr int BLOAD = BK * BN / THREADS;
    __shared__ float As[BK][BM + 1];
    __shared__ float Bs[BK][BN];

    const int tid = threadIdx.x;
    const int tx = tid % (BN / TN);
    const int ty = tid / (BN / TN);
    const int m0 = blockIdx.y * BM;
    const int n0 = blockIdx.x * BN;

    // Resolve A row indices once (gather support for embedding lookup)
    int arow[ALOAD];
#pragma unroll
    for (int l = 0; l < ALOAD; l++) {
        int idx = tid + l * THREADS;
        int m = idx / BK;
        arow[l] = rowidx ? rowidx[m0 + m] : (m0 + m);
    }

    float acc[TM][TN];
#pragma unroll
    for (int i = 0; i < TM; i++)
#pragma unroll
        for (int j = 0; j < TN; j++) acc[i][j] = 0.f;

    for (int k0 = 0; k0 < K; k0 += BK) {
#pragma unroll
        for (int l = 0; l < ALOAD; l++) {
            int idx = tid + l * THREADS;
            int k = idx % BK, m = idx / BK;
            As[k][m] = A[(size_t)arow[l] * lda + k0 + k];
        }
#pragma unroll
        for (int l = 0; l < BLOAD; l++) {
            int idx = tid + l * THREADS;
            int n = idx % BN, k = idx / BN;
            Bs[k][n] = B[(size_t)(k0 + k) * ldb + n0 + n];
        }
        __syncthreads();
#pragma unroll
        for (int kk = 0; kk < BK; kk++) {
            float a[TM], b[TN];
#pragma unroll
            for (int i = 0; i < TM; i++) a[i] = As[kk][ty * TM + i];
#pragma unroll
            for (int j = 0; j < TN; j++) b[j] = Bs[kk][tx * TN + j];
#pragma unroll
            for (int i = 0; i < TM; i++)
#pragma unroll
                for (int j = 0; j < TN; j++) acc[i][j] += a[i] * b[j];
        }
        __syncthreads();
    }

#pragma unroll
    for (int i = 0; i < TM; i++) {
        int m = m0 + ty * TM + i;
#pragma unroll
        for (int j = 0; j < TN; j++) {
            int n = n0 + tx * TN + j;
            float v = acc[i][j];
            if (bias) v += bias[n];
            if (add)  v += add[(size_t)m * ldadd + n];
            C[(size_t)m * ldc + n] = v;
        }
    }
}

// ---------------- LSTM gate elementwise ----------------
__device__ __forceinline__ float sigmoidf_(float x) { return 1.f / (1.f + __expf(-x)); }

__global__ void lstm_gate_kernel(int t) {
    int idx = blockIdx.x * blockDim.x + threadIdx.x;
    if (idx >= NB * HH) return;
    int n = idx >> 9, j = idx & (HH - 1);
    const float* Ar = g_A + (size_t)n * G4;
    float i_ = sigmoidf_(Ar[j]);
    float f_ = sigmoidf_(Ar[HH + j]);
    float o_ = sigmoidf_(Ar[2 * HH + j]);
    float gg = tanhf(Ar[3 * HH + j]);
    float cp = (t == 0) ? 0.f : g_c[idx];
    float c = f_ * cp + i_ * gg;
    float h = o_ * tanhf(c);
    g_c[idx] = c;
    g_h[idx] = h;
    g_h_all[((size_t)(n * TT + t)) * HH + j] = h;
}

// ---------------- vocab GEMM fused with sum-exp epilogue ----------------
// scores bounded (|h|<1, Var<=1) -> exp without max subtraction is safe in fp32.
__global__ void __launch_bounds__(256)
vocab_lse_kernel(const float* __restrict__ Wv, const float* __restrict__ bv) {
    constexpr int BM = 64, BN = 64, BK = 16, TM = 4, TN = 4;
    __shared__ float As[BK][BM + 1];
    __shared__ float Bs[BK][BN];
    const int tid = threadIdx.x;
    const int tx = tid & 15;
    const int ty = tid >> 4;
    const int m0 = blockIdx.y * BM;
    const int n0 = blockIdx.x * BN;

    float acc[TM][TN];
#pragma unroll
    for (int i = 0; i < TM; i++)
#pragma unroll
        for (int j = 0; j < TN; j++) acc[i][j] = 0.f;

    for (int k0 = 0; k0 < HH; k0 += BK) {
#pragma unroll
        for (int l = 0; l < 4; l++) {
            int idx = tid + l * 256;
            int k = idx & 15, m = idx >> 4;
            As[k][m] = g_h_all[(size_t)(m0 + m) * HH + k0 + k];
        }
#pragma unroll
        for (int l = 0; l < 4; l++) {
            int idx = tid + l * 256;
            int n = idx & 63, k = idx >> 6;
            Bs[k][n] = Wv[(size_t)(k0 + k) * VV + n0 + n];
        }
        __syncthreads();
#pragma unroll
        for (int kk = 0; kk < BK; kk++) {
            float a[TM], b[TN];
#pragma unroll
            for (int i = 0; i < TM; i++) a[i] = As[kk][ty * TM + i];
#pragma unroll
            for (int j = 0; j < TN; j++) b[j] = Bs[kk][tx * TN + j];
#pragma unroll
            for (int i = 0; i < TM; i++)
#pragma unroll
                for (int j = 0; j < TN; j++) acc[i][j] += a[i] * b[j];
        }
        __syncthreads();
    }

    float bvr[TN];
#pragma unroll
    for (int j = 0; j < TN; j++) bvr[j] = bv[n0 + tx * TN + j];

#pragma unroll
    for (int i = 0; i < TM; i++) {
        float rs = 0.f;
#pragma unroll
        for (int j = 0; j < TN; j++) rs += __expf(acc[i][j] + bvr[j]);
#pragma unroll
        for (int off = 8; off; off >>= 1)
            rs += __shfl_down_sync(0xffffffffu, rs, off, 16);
        if (tx == 0)
            g_part[(size_t)(m0 + ty * TM + i) * NTILES_V + blockIdx.x] = rs;
    }
}

// ---------------- target scores: one warp per (n,t) ----------------
__global__ void tscore_kernel(const float* __restrict__ Wv, const float* __restrict__ bv) {
    int w = (blockIdx.x * blockDim.x + threadIdx.x) >> 5;
    int lane = threadIdx.x & 31;
    if (w >= M_NT) return;
    int tgt = g_tgt[w];
    const float* h = g_h_all + (size_t)w * HH;
    float s = 0.f;
    for (int k = lane; k < HH; k += 32) s += h[k] * Wv[(size_t)k * VV + tgt];
#pragma unroll
    for (int off = 16; off; off >>= 1) s += __shfl_down_sync(0xffffffffu, s, off);
    if (lane == 0) g_tsc[w] = s + bv[tgt];
}

// ---------------- per-token nll (deterministic warp reduce of 500 partials) --
__global__ void nll_kernel() {
    int w = (blockIdx.x * blockDim.x + threadIdx.x) >> 5;
    int lane = threadIdx.x & 31;
    if (w >= M_NT) return;
    const float* p = g_part + (size_t)w * NTILES_V;
    float s = 0.f;
    for (int i = lane; i < NTILES_V; i += 32) s += p[i];
#pragma unroll
    for (int off = 16; off; off >>= 1) s += __shfl_down_sync(0xffffffffu, s, off);
    if (lane == 0)
        g_nll[w] = (g_tgt[w] != 0) ? (logf(s) - g_tsc[w]) : 0.f;
}

// ---------------- final deterministic reduction ----------------
__global__ void loss_kernel(float* __restrict__ out) {
    __shared__ float sm[256];
    float s = 0.f;
    for (int i = threadIdx.x; i < M_NT; i += 256) s += g_nll[i];
    sm[threadIdx.x] = s;
    __syncthreads();
    for (int off = 128; off; off >>= 1) {
        if (threadIdx.x < off) sm[threadIdx.x] += sm[threadIdx.x + off];
        __syncthreads();
    }
    if (threadIdx.x == 0) out[0] = sm[0] / (float)NB;
}

// ---------------- launch ----------------
extern "C" void kernel_launch(void* const* d_in, const int* in_sizes, int n_in,
                              void* d_out, int out_size) {
    const float* features = (const float*)d_in[0];
    const void*  captions =               d_in[1];
    const float* W_proj   = (const float*)d_in[2];
    const float* b_proj   = (const float*)d_in[3];
    const float* W_embed  = (const float*)d_in[4];
    const float* Wx       = (const float*)d_in[5];
    const float* Wh       = (const float*)d_in[6];
    const float* bb       = (const float*)d_in[7];
    const float* W_vocab  = (const float*)d_in[8];
    const float* b_vocab  = (const float*)d_in[9];
    float* out = (float*)d_out;

    float *p_XWx, *p_h, *p_A;
    cudaGetSymbolAddress((void**)&p_XWx, g_XWx);
    cudaGetSymbolAddress((void**)&p_h,   g_h);
    cudaGetSymbolAddress((void**)&p_A,   g_A);

    // 0. caption dtype + index tables
    detect_kernel<<<1, 256>>>((const unsigned int*)captions);
    build_idx_kernel<<<(M_NT + 255) / 256, 256>>>(captions);

    int *p_rows;
    cudaGetSymbolAddress((void**)&p_rows, g_rows);

    // 1. h0 = features @ W_proj + b_proj   (M=128, K=1280, N=512)
    sgemm_k<64, 64, 16, 4, 4><<<dim3(HH / 64, NB / 64), 256>>>(
        features, DF, W_proj, HH, p_h, HH, b_proj, nullptr, 0, nullptr, DF);

    // 2. XWx[(n,t), :] = W_embed[captions_in] @ Wx + b   (M=4096, K=256, N=2048)
    sgemm_k<64, 64, 16, 4, 4><<<dim3(G4 / 64, M_NT / 64), 256>>>(
        W_embed, WD, Wx, G4, p_XWx, G4, bb, nullptr, 0, p_rows, WD);

    // 3. LSTM: 32 serial steps of (A = XWx_t + h @ Wh) then gates
    for (int t = 0; t < TT; t++) {
        sgemm_k<32, 64, 16, 2, 4><<<dim3(G4 / 64, NB / 32), 256>>>(
            p_h, HH, Wh, G4, p_A, G4, nullptr,
            p_XWx + (size_t)t * G4, TT * G4, nullptr, HH);
        lstm_gate_kernel<<<(NB * HH + 255) / 256, 256>>>(t);
    }

    // 4. vocab GEMM + fused sum-exp partials  (M=4096, K=512, N=32000)
    vocab_lse_kernel<<<dim3(NTILES_V, M_NT / 64), 256>>>(W_vocab, b_vocab);

    // 5. target scores, per-token nll, final loss
    tscore_kernel<<<M_NT / 4, 128>>>(W_vocab, b_vocab);
    nll_kernel<<<M_NT / 4, 128>>>();
    loss_kernel<<<1, 256>>>(out);
}

// round 2
// speedup vs baseline: 3.0432x; 3.0432x over previous
#include <cuda_runtime.h>
#include <cuda_bf16.h>
#include <math.h>
#include <stdint.h>

// Problem constants
#define NB   128
#define TT   32
#define NTOK (128*33)
#define DF   1280
#define WD   256
#define HH   512
#define VV   32000
#define M_NT (NB*TT)      // 4096
#define G4   2048
#define VBM  128
#define VBN  128
#define VBK  32
#define NTILES_V (VV/VBN) // 250

// ---------------- device scratch ----------------
__device__ float g_XWx[(size_t)M_NT * G4];          // gate-interleaved x@Wx + b
__device__ float g_h_all[(size_t)M_NT * HH];
__device__ __nv_bfloat16 g_hb[(size_t)M_NT * HH];   // bf16 h_all
__device__ __nv_bfloat16 g_wt[(size_t)VV * HH];     // W_vocab bf16, k-major [n][k]
__device__ float g_hbuf[2][NB * HH];
__device__ float g_c[NB * HH];
__device__ float g_Wxi[WD * G4];                    // gate-interleaved Wx
__device__ float g_Whi[HH * G4];
__device__ float g_bi[G4];
__device__ float g_part[(size_t)M_NT * NTILES_V];
__device__ float g_tsc[M_NT];
__device__ float g_nll[M_NT];
__device__ int   g_rows[M_NT];
__device__ int   g_tgt[M_NT];
__device__ int   g_is64;

// ---------------- small helpers ----------------
__device__ __forceinline__ float sigmoidf_(float x) { return 1.f / (1.f + __expf(-x)); }

__device__ __forceinline__ uint32_t smem_u32(const void* p) {
    return (uint32_t)__cvta_generic_to_shared(p);
}
__device__ __forceinline__ void cp16(void* dst, const void* src) {
    asm volatile("cp.async.cg.shared.global [%0], [%1], 16;"
                 :: "r"(smem_u32(dst)), "l"(src));
}
__device__ __forceinline__ void cp_commit() { asm volatile("cp.async.commit_group;"); }
template<int N> __device__ __forceinline__ void cp_wait() {
    asm volatile("cp.async.wait_group %0;" :: "n"(N));
}
__device__ __forceinline__ void ldsm4(uint32_t& r0, uint32_t& r1, uint32_t& r2, uint32_t& r3, uint32_t addr) {
    asm volatile("ldmatrix.sync.aligned.m8n8.x4.shared.b16 {%0,%1,%2,%3}, [%4];"
                 : "=r"(r0), "=r"(r1), "=r"(r2), "=r"(r3) : "r"(addr));
}
__device__ __forceinline__ void ldsm2(uint32_t& r0, uint32_t& r1, uint32_t addr) {
    asm volatile("ldmatrix.sync.aligned.m8n8.x2.shared.b16 {%0,%1}, [%2];"
                 : "=r"(r0), "=r"(r1) : "r"(addr));
}
__device__ __forceinline__ void mma16816(float* c, const uint32_t* a, const uint32_t* b) {
    asm volatile("mma.sync.aligned.m16n8k16.row.col.f32.bf16.bf16.f32 "
                 "{%0,%1,%2,%3}, {%4,%5,%6,%7}, {%8,%9}, {%0,%1,%2,%3};"
                 : "+f"(c[0]), "+f"(c[1]), "+f"(c[2]), "+f"(c[3])
                 : "r"(a[0]), "r"(a[1]), "r"(a[2]), "r"(a[3]), "r"(b[0]), "r"(b[1]));
}

// ---------------- caption dtype detection + index build ----------------
__global__ void detect_kernel(const unsigned int* __restrict__ w) {
    __shared__ int found;
    if (threadIdx.x == 0) found = 0;
    __syncthreads();
    for (int i = threadIdx.x; i < NTOK / 2; i += blockDim.x)
        if (w[2 * i + 1] != 0u) found = 1;
    __syncthreads();
    if (threadIdx.x == 0) g_is64 = (found == 0) ? 1 : 0;
}

__global__ void build_idx_kernel(const void* __restrict__ caps) {
    int m = blockIdx.x * blockDim.x + threadIdx.x;
    if (m >= M_NT) return;
    int n = m >> 5, t = m & 31;
    int ci, co;
    if (g_is64) {
        const long long* c = (const long long*)caps;
        ci = (int)c[n * 33 + t];  co = (int)c[n * 33 + t + 1];
    } else {
        const int* c = (const int*)caps;
        ci = c[n * 33 + t];       co = c[n * 33 + t + 1];
    }
    g_rows[m] = ci;  g_tgt[m] = co;
}

// ---------------- gate-interleave reorder: out[w][j*4+g] = in[w][g*512+j] ----
__global__ void reorder_kernel(const float* __restrict__ in, float* __restrict__ out, int W) {
    int idx = blockIdx.x * blockDim.x + threadIdx.x;
    if (idx >= W * G4) return;
    int w = idx / G4, np = idx % G4;
    int j = np >> 2, g = np & 3;
    out[idx] = in[(size_t)w * G4 + g * HH + j];
}

// ---------------- generic tiled SGEMM (fp32) ----------------
template<int BM, int BN, int BK, int TM, int TN>
__global__ void __launch_bounds__(256)
sgemm_k(const float* __restrict__ A, int lda,
        const float* __restrict__ B, int ldb,
        float* __restrict__ C, int ldc,
        const float* __restrict__ bias,
        const int* __restrict__ rowidx,
        int K)
{
    constexpr int THREADS = (BM / TM) * (BN / TN);
    constexpr int ALOAD = BM * BK / THREADS;
    constexpr int BLOAD = BK * BN / THREADS;
    __shared__ float As[BK][BM + 1];
    __shared__ float Bs[BK][BN];

    const int tid = threadIdx.x;
    const int tx = tid % (BN / TN);
    const int ty = tid / (BN / TN);
    const int m0 = blockIdx.y * BM;
    const int n0 = blockIdx.x * BN;

    int arow[ALOAD];
#pragma unroll
    for (int l = 0; l < ALOAD; l++) {
        int idx = tid + l * THREADS;
        int m = idx / BK;
        arow[l] = rowidx ? rowidx[m0 + m] : (m0 + m);
    }

    float acc[TM][TN];
#pragma unroll
    for (int i = 0; i < TM; i++)
#pragma unroll
        for (int j = 0; j < TN; j++) acc[i][j] = 0.f;

    for (int k0 = 0; k0 < K; k0 += BK) {
#pragma unroll
        for (int l = 0; l < ALOAD; l++) {
            int idx = tid + l * THREADS;
            int k = idx % BK, m = idx / BK;
            As[k][m] = A[(size_t)arow[l] * lda + k0 + k];
        }
#pragma unroll
        for (int l = 0; l < BLOAD; l++) {
            int idx = tid + l * THREADS;
            int n = idx % BN, k = idx / BN;
            Bs[k][n] = B[(size_t)(k0 + k) * ldb + n0 + n];
        }
        __syncthreads();
#pragma unroll
        for (int kk = 0; kk < BK; kk++) {
            float a[TM], b[TN];
#pragma unroll
            for (int i = 0; i < TM; i++) a[i] = As[kk][ty * TM + i];
#pragma unroll
            for (int j = 0; j < TN; j++) b[j] = Bs[kk][tx * TN + j];
#pragma unroll
            for (int i = 0; i < TM; i++)
#pragma unroll
                for (int j = 0; j < TN; j++) acc[i][j] += a[i] * b[j];
        }
        __syncthreads();
    }

#pragma unroll
    for (int i = 0; i < TM; i++) {
        int m = m0 + ty * TM + i;
#pragma unroll
        for (int j = 0; j < TN; j++) {
            int n = n0 + tx * TN + j;
            float v = acc[i][j];
            if (bias) v += bias[n];
            C[(size_t)m * ldc + n] = v;
        }
    }
}

// ---------------- LSTM step: GEMM + fused gates (gate-interleaved cols) -----
__global__ void __launch_bounds__(256)
lstm_step_fused(const float* __restrict__ Whi, const float* __restrict__ hin,
                float* __restrict__ hout, int t)
{
    constexpr int BM = 32, BN = 64, BK = 16;
    __shared__ float As[BK][BM + 1];
    __shared__ float Bs[BK][BN];
    int tid = threadIdx.x;
    int tx = tid & 15, ty = tid >> 4;
    int m0 = blockIdx.y * BM, n0 = blockIdx.x * BN;

    float acc[2][4] = {};
    for (int k0 = 0; k0 < HH; k0 += BK) {
#pragma unroll
        for (int l = 0; l < 2; l++) {
            int idx = tid + l * 256;
            int k = idx & 15, m = idx >> 4;
            As[k][m] = hin[(m0 + m) * HH + k0 + k];
        }
#pragma unroll
        for (int l = 0; l < 4; l++) {
            int idx = tid + l * 256;
            int n = idx & 63, k = idx >> 6;
            Bs[k][n] = Whi[(size_t)(k0 + k) * G4 + n0 + n];
        }
        __syncthreads();
#pragma unroll
        for (int kk = 0; kk < BK; kk++) {
            float a0 = As[kk][ty * 2], a1 = As[kk][ty * 2 + 1];
            float b[4];
#pragma unroll
            for (int j = 0; j < 4; j++) b[j] = Bs[kk][tx * 4 + j];
#pragma unroll
            for (int j = 0; j < 4; j++) { acc[0][j] += a0 * b[j]; acc[1][j] += a1 * b[j]; }
        }
        __syncthreads();
    }

    int j = (n0 >> 2) + tx;
#pragma unroll
    for (int i = 0; i < 2; i++) {
        int m = m0 + ty * 2 + i;
        const float* xr = g_XWx + ((size_t)((m << 5) + t)) * G4 + n0 + tx * 4;
        float i_ = sigmoidf_(acc[i][0] + xr[0]);
        float f_ = sigmoidf_(acc[i][1] + xr[1]);
        float o_ = sigmoidf_(acc[i][2] + xr[2]);
        float gg = tanhf(acc[i][3] + xr[3]);
        float cp = (t == 0) ? 0.f : g_c[m * HH + j];
        float c = f_ * cp + i_ * gg;
        float h = o_ * tanhf(c);
        g_c[m * HH + j] = c;
        hout[m * HH + j] = h;
        g_h_all[((size_t)((m << 5) + t)) * HH + j] = h;
    }
}

// ---------------- conversions ----------------
__global__ void convH_kernel() {
    int i = blockIdx.x * blockDim.x + threadIdx.x;
    if (i < M_NT * HH) g_hb[i] = __float2bfloat16(g_h_all[i]);
}

// W_vocab fp32 [k=512][n=32000] -> g_wt bf16 [n][k] (k-major)
__global__ void convW_kernel(const float* __restrict__ Wv) {
    __shared__ float tile[32][33];
    int n0 = blockIdx.x * 32, k0 = blockIdx.y * 32;
    int tx = threadIdx.x, ty = threadIdx.y;   // 32 x 8
#pragma unroll
    for (int r = 0; r < 4; r++)
        tile[ty + r * 8][tx] = Wv[(size_t)(k0 + ty + r * 8) * VV + n0 + tx];
    __syncthreads();
#pragma unroll
    for (int r = 0; r < 4; r++) {
        int n = ty + r * 8;
        g_wt[(size_t)(n0 + n) * HH + k0 + tx] = __float2bfloat16(tile[tx][n]);
    }
}

// ---------------- vocab bf16 MMA GEMM + fused sum-exp epilogue --------------
__global__ void __launch_bounds__(256)
vocab_mma_kernel(const float* __restrict__ bv) {
    __shared__ __align__(16) __nv_bfloat16 As[2][VBM][40];   // 80B rows: no ldsm conflicts
    __shared__ __align__(16) __nv_bfloat16 Bs[2][VBN][40];
    __shared__ float sred[4][VBM];

    int tid = threadIdx.x;
    int lane = tid & 31, wid = tid >> 5;
    int wm = wid & 1, wn = wid >> 1;          // 2x4 warp grid: 64 rows x 32 cols each
    int m0 = blockIdx.x * VBM;                // 32 m-tiles (fast dim: share B tile)
    int n0 = blockIdx.y * VBN;                // 250 n-tiles

    float acc[4][4][4];
#pragma unroll
    for (int a = 0; a < 4; a++)
#pragma unroll
        for (int b = 0; b < 4; b++)
#pragma unroll
            for (int c = 0; c < 4; c++) acc[a][b][c] = 0.f;

    auto loadA = [&](int s, int k0) {
#pragma unroll
        for (int l = 0; l < 2; l++) {
            int idx = tid + l * 256;
            int row = idx >> 2, ch = idx & 3;
            cp16(&As[s][row][ch * 8], g_hb + (size_t)(m0 + row) * HH + k0 + ch * 8);
        }
    };
    auto loadB = [&](int s, int k0) {
#pragma unroll
        for (int l = 0; l < 2; l++) {
            int idx = tid + l * 256;
            int row = idx >> 2, ch = idx & 3;
            cp16(&Bs[s][row][ch * 8], g_wt + (size_t)(n0 + row) * HH + k0 + ch * 8);
        }
    };

    loadA(0, 0); loadB(0, 0); cp_commit();

    constexpr int NIT = HH / VBK;  // 16
    for (int it = 0; it < NIT; it++) {
        if (it + 1 < NIT) {
            int s = (it + 1) & 1;
            loadA(s, (it + 1) * VBK); loadB(s, (it + 1) * VBK);
            cp_commit();
            cp_wait<1>();
        } else {
            cp_wait<0>();
        }
        __syncthreads();
        int s = it & 1;
        uint32_t aBase = smem_u32(&As[s][0][0]);
        uint32_t bBase = smem_u32(&Bs[s][0][0]);
#pragma unroll
        for (int ks = 0; ks < 2; ks++) {
            uint32_t a[4][4], b[4][2];
#pragma unroll
            for (int mf = 0; mf < 4; mf++) {
                int row = wm * 64 + mf * 16 + (lane & 15);
                uint32_t addr = aBase + row * 80 + (ks * 16 + (lane >> 4) * 8) * 2;
                ldsm4(a[mf][0], a[mf][1], a[mf][2], a[mf][3], addr);
            }
#pragma unroll
            for (int nf = 0; nf < 4; nf++) {
                int row = wn * 32 + nf * 8 + (lane & 7);
                uint32_t addr = bBase + row * 80 + (ks * 16 + ((lane >> 3) & 1) * 8) * 2;
                ldsm2(b[nf][0], b[nf][1], addr);
            }
#pragma unroll
            for (int mf = 0; mf < 4; mf++)
#pragma unroll
                for (int nf = 0; nf < 4; nf++)
                    mma16816(acc[mf][nf], a[mf], b[nf]);
        }
        __syncthreads();
    }

    // epilogue: exp(score + bias) row sums. Scores bounded (|h|<1, Var<=1).
    float rowsum[4][2] = {};
#pragma unroll
    for (int nf = 0; nf < 4; nf++) {
        int nb_ = n0 + wn * 32 + nf * 8 + 2 * (lane & 3);
        float b0 = bv[nb_], b1 = bv[nb_ + 1];
#pragma unroll
        for (int mf = 0; mf < 4; mf++) {
            rowsum[mf][0] += __expf(acc[mf][nf][0] + b0) + __expf(acc[mf][nf][1] + b1);
            rowsum[mf][1] += __expf(acc[mf][nf][2] + b0) + __expf(acc[mf][nf][3] + b1);
        }
    }
#pragma unroll
    for (int mf = 0; mf < 4; mf++)
#pragma unroll
        for (int h = 0; h < 2; h++) {
            rowsum[mf][h] += __shfl_xor_sync(0xffffffffu, rowsum[mf][h], 1);
            rowsum[mf][h] += __shfl_xor_sync(0xffffffffu, rowsum[mf][h], 2);
        }
    if ((lane & 3) == 0) {
#pragma unroll
        for (int mf = 0; mf < 4; mf++) {
            int r = wm * 64 + mf * 16 + (lane >> 2);
            sred[wn][r]     = rowsum[mf][0];
            sred[wn][r + 8] = rowsum[mf][1];
        }
    }
    __syncthreads();
    if (tid < VBM) {
        float s = sred[0][tid] + sred[1][tid] + sred[2][tid] + sred[3][tid];
        g_part[(size_t)(m0 + tid) * NTILES_V + blockIdx.y] = s;
    }
}

// ---------------- target scores / nll / loss ----------------
__global__ void tscore_kernel(const float* __restrict__ Wv, const float* __restrict__ bv) {
    int w = (blockIdx.x * blockDim.x + threadIdx.x) >> 5;
    int lane = threadIdx.x & 31;
    if (w >= M_NT) return;
    int tgt = g_tgt[w];
    const float* h = g_h_all + (size_t)w * HH;
    float s = 0.f;
    for (int k = lane; k < HH; k += 32) s += h[k] * Wv[(size_t)k * VV + tgt];
#pragma unroll
    for (int off = 16; off; off >>= 1) s += __shfl_down_sync(0xffffffffu, s, off);
    if (lane == 0) g_tsc[w] = s + bv[tgt];
}

__global__ void nll_kernel() {
    int w = (blockIdx.x * blockDim.x + threadIdx.x) >> 5;
    int lane = threadIdx.x & 31;
    if (w >= M_NT) return;
    const float* p = g_part + (size_t)w * NTILES_V;
    float s = 0.f;
    for (int i = lane; i < NTILES_V; i += 32) s += p[i];
#pragma unroll
    for (int off = 16; off; off >>= 1) s += __shfl_down_sync(0xffffffffu, s, off);
    if (lane == 0)
        g_nll[w] = (g_tgt[w] != 0) ? (logf(s) - g_tsc[w]) : 0.f;
}

__global__ void loss_kernel(float* __restrict__ out) {
    __shared__ float sm[256];
    float s = 0.f;
    for (int i = threadIdx.x; i < M_NT; i += 256) s += g_nll[i];
    sm[threadIdx.x] = s;
    __syncthreads();
    for (int off = 128; off; off >>= 1) {
        if (threadIdx.x < off) sm[threadIdx.x] += sm[threadIdx.x + off];
        __syncthreads();
    }
    if (threadIdx.x == 0) out[0] = sm[0] / (float)NB;
}

// ---------------- launch ----------------
extern "C" void kernel_launch(void* const* d_in, const int* in_sizes, int n_in,
                              void* d_out, int out_size) {
    const float* features = (const float*)d_in[0];
    const void*  captions =               d_in[1];
    const float* W_proj   = (const float*)d_in[2];
    const float* b_proj   = (const float*)d_in[3];
    const float* W_embed  = (const float*)d_in[4];
    const float* Wx       = (const float*)d_in[5];
    const float* Wh       = (const float*)d_in[6];
    const float* bb       = (const float*)d_in[7];
    const float* W_vocab  = (const float*)d_in[8];
    const float* b_vocab  = (const float*)d_in[9];
    float* out = (float*)d_out;

    float *p_XWx, *p_hbuf, *p_Wxi, *p_Whi, *p_bi;
    int *p_rows;
    cudaGetSymbolAddress((void**)&p_XWx,  g_XWx);
    cudaGetSymbolAddress((void**)&p_hbuf, g_hbuf);
    cudaGetSymbolAddress((void**)&p_Wxi,  g_Wxi);
    cudaGetSymbolAddress((void**)&p_Whi,  g_Whi);
    cudaGetSymbolAddress((void**)&p_bi,   g_bi);
    cudaGetSymbolAddress((void**)&p_rows, g_rows);

    // 0. caption dtype + index tables, weight reorders, W_vocab conversion
    detect_kernel<<<1, 256>>>((const unsigned int*)captions);
    build_idx_kernel<<<(M_NT + 255) / 256, 256>>>(captions);
    reorder_kernel<<<(WD * G4 + 255) / 256, 256>>>(Wx, p_Wxi, WD);
    reorder_kernel<<<(HH * G4 + 255) / 256, 256>>>(Wh, p_Whi, HH);
    reorder_kernel<<<(G4 + 255) / 256, 256>>>(bb, p_bi, 1);
    convW_kernel<<<dim3(VV / 32, HH / 32), dim3(32, 8)>>>(W_vocab);

    // 1. h0 = features @ W_proj + b_proj
    sgemm_k<64, 64, 16, 4, 4><<<dim3(HH / 64, NB / 64), 256>>>(
        features, DF, W_proj, HH, p_hbuf, HH, b_proj, nullptr, DF);

    // 2. XWx (gate-interleaved) = W_embed[captions_in] @ Wxi + bi
    sgemm_k<64, 64, 16, 4, 4><<<dim3(G4 / 64, M_NT / 64), 256>>>(
        W_embed, WD, p_Wxi, G4, p_XWx, G4, p_bi, p_rows, WD);

    // 3. LSTM: 32 serial fused steps (double-buffered h)
    for (int t = 0; t < TT; t++) {
        lstm_step_fused<<<dim3(G4 / 64, NB / 32), 256>>>(
            p_Whi, p_hbuf + (t & 1) * (NB * HH), p_hbuf + ((t + 1) & 1) * (NB * HH), t);
    }

    // 4. h -> bf16, vocab bf16 MMA GEMM + fused sum-exp
    convH_kernel<<<(M_NT * HH + 255) / 256, 256>>>();
    vocab_mma_kernel<<<dim3(M_NT / VBM, NTILES_V), 256>>>(b_vocab);

    // 5. target scores, per-token nll, final loss
    tscore_kernel<<<M_NT / 4, 128>>>(W_vocab, b_vocab);
    nll_kernel<<<M_NT / 4, 128>>>();
    loss_kernel<<<1, 256>>>(out);
}

// round 3
// speedup vs baseline: 4.3576x; 1.4319x over previous
#include <cuda_runtime.h>
#include <cuda_bf16.h>
#include <math.h>
#include <stdint.h>

// Problem constants
#define NB   128
#define TT   32
#define NTOK (128*33)
#define DF   1280
#define WD   256
#define HH   512
#define VV   32000
#define M_NT (NB*TT)      // 4096
#define G4   2048
#define VBM  128
#define VBN  128
#define VBK  32
#define NTILES_V (VV/VBN) // 250

// ---------------- device scratch ----------------
__device__ __nv_bfloat16 g_hb[(size_t)M_NT * HH];    // h_all bf16, [(n*32+t)][512]
__device__ __nv_bfloat16 g_wt[(size_t)VV * HH];      // W_vocab bf16 [n][k]
__device__ __nv_bfloat16 g_WxiT[(size_t)G4 * WD];    // gate-interleaved Wx, [n][k] bf16
__device__ __nv_bfloat16 g_WhiT[(size_t)G4 * HH];    // gate-interleaved Wh, [n][k] bf16
__device__ __nv_bfloat16 g_xg[(size_t)M_NT * WD];    // gathered embeddings bf16
__device__ float g_XWx[(size_t)M_NT * G4];           // gate-interleaved x@Wx + b
__device__ float g_h0[NB * HH];
__device__ __nv_bfloat16 g_h0b[NB * HH];
__device__ float g_c[NB * HH];
__device__ float g_bi[G4];
__device__ float g_part[(size_t)M_NT * NTILES_V];
__device__ float g_tsc[M_NT];
__device__ float g_nll[M_NT];
__device__ int   g_rows[M_NT];
__device__ int   g_tgt[M_NT];
__device__ int   g_is64;

// ---------------- small helpers ----------------
__device__ __forceinline__ float sigmoidf_(float x) { return 1.f / (1.f + __expf(-x)); }
__device__ __forceinline__ uint32_t smem_u32(const void* p) {
    return (uint32_t)__cvta_generic_to_shared(p);
}
__device__ __forceinline__ void cp16(void* dst, const void* src) {
    asm volatile("cp.async.cg.shared.global [%0], [%1], 16;"
                 :: "r"(smem_u32(dst)), "l"(src));
}
__device__ __forceinline__ void cp_commit() { asm volatile("cp.async.commit_group;"); }
template<int N> __device__ __forceinline__ void cp_wait() {
    asm volatile("cp.async.wait_group %0;" :: "n"(N));
}
__device__ __forceinline__ void ldsm4(uint32_t& r0, uint32_t& r1, uint32_t& r2, uint32_t& r3, uint32_t addr) {
    asm volatile("ldmatrix.sync.aligned.m8n8.x4.shared.b16 {%0,%1,%2,%3}, [%4];"
                 : "=r"(r0), "=r"(r1), "=r"(r2), "=r"(r3) : "r"(addr));
}
__device__ __forceinline__ void ldsm2(uint32_t& r0, uint32_t& r1, uint32_t addr) {
    asm volatile("ldmatrix.sync.aligned.m8n8.x2.shared.b16 {%0,%1}, [%2];"
                 : "=r"(r0), "=r"(r1) : "r"(addr));
}
__device__ __forceinline__ void mma16816(float* c, const uint32_t* a, const uint32_t* b) {
    asm volatile("mma.sync.aligned.m16n8k16.row.col.f32.bf16.bf16.f32 "
                 "{%0,%1,%2,%3}, {%4,%5,%6,%7}, {%8,%9}, {%0,%1,%2,%3};"
                 : "+f"(c[0]), "+f"(c[1]), "+f"(c[2]), "+f"(c[3])
                 : "r"(a[0]), "r"(a[1]), "r"(a[2]), "r"(a[3]), "r"(b[0]), "r"(b[1]));
}

// ---------------- caption dtype detection + index build ----------------
__global__ void detect_kernel(const unsigned int* __restrict__ w) {
    __shared__ int found;
    if (threadIdx.x == 0) found = 0;
    __syncthreads();
    for (int i = threadIdx.x; i < NTOK / 2; i += blockDim.x)
        if (w[2 * i + 1] != 0u) found = 1;
    __syncthreads();
    if (threadIdx.x == 0) g_is64 = (found == 0) ? 1 : 0;
}

__global__ void build_idx_kernel(const void* __restrict__ caps) {
    int m = blockIdx.x * blockDim.x + threadIdx.x;
    if (m >= M_NT) return;
    int n = m >> 5, t = m & 31;
    int ci, co;
    if (g_is64) {
        const long long* c = (const long long*)caps;
        ci = (int)c[n * 33 + t];  co = (int)c[n * 33 + t + 1];
    } else {
        const int* c = (const int*)caps;
        ci = c[n * 33 + t];       co = c[n * 33 + t + 1];
    }
    g_rows[m] = ci;  g_tgt[m] = co;
}

// ---------------- bias gate-interleave: out[j*4+g] = in[g*512+j] ----------
__global__ void reorder_bias_kernel(const float* __restrict__ in, float* __restrict__ out) {
    int np = blockIdx.x * blockDim.x + threadIdx.x;
    if (np >= G4) return;
    int j = np >> 2, g = np & 3;
    out[np] = in[g * HH + j];
}

// ---- transpose + gate-interleave + bf16: out[(j*4+g)][k] = in[k][g*512+j] --
__global__ void transT_gate_kernel(const float* __restrict__ in, __nv_bfloat16* __restrict__ out, int K) {
    __shared__ float tile[32][33];
    int np0 = blockIdx.x * 32, k0 = blockIdx.y * 32;
    int tx = threadIdx.x, ty = threadIdx.y;  // 32 x 8
#pragma unroll
    for (int r = 0; r < 4; r++)
        tile[ty + r * 8][tx] = in[(size_t)(k0 + ty + r * 8) * G4 + np0 + tx];
    __syncthreads();
#pragma unroll
    for (int r = 0; r < 4; r++) {
        int npl = ty + r * 8;
        int np = np0 + npl;
        int g = np >> 9, j = np & 511;
        int n = (j << 2) + g;
        out[(size_t)n * K + k0 + tx] = __float2bfloat16(tile[tx][npl]);
    }
}

// ---- W_vocab fp32 [k][n] -> bf16 [n][k] -----------------------------------
__global__ void convW_kernel(const float* __restrict__ Wv) {
    __shared__ float tile[32][33];
    int n0 = blockIdx.x * 32, k0 = blockIdx.y * 32;
    int tx = threadIdx.x, ty = threadIdx.y;
#pragma unroll
    for (int r = 0; r < 4; r++)
        tile[ty + r * 8][tx] = Wv[(size_t)(k0 + ty + r * 8) * VV + n0 + tx];
    __syncthreads();
#pragma unroll
    for (int r = 0; r < 4; r++) {
        int n = ty + r * 8;
        g_wt[(size_t)(n0 + n) * HH + k0 + tx] = __float2bfloat16(tile[tx][n]);
    }
}

// ---- gather + convert embeddings: g_xg[m][k] = bf16(W_embed[rows[m]][k]) --
__global__ void gatherconv_kernel(const float* __restrict__ We) {
    int idx = blockIdx.x * blockDim.x + threadIdx.x;
    if (idx >= M_NT * WD) return;
    int m = idx >> 8, k = idx & (WD - 1);
    g_xg[idx] = __float2bfloat16(We[(size_t)g_rows[m] * WD + k]);
}

__global__ void convh0_kernel() {
    int i = blockIdx.x * blockDim.x + threadIdx.x;
    if (i < NB * HH) g_h0b[i] = __float2bfloat16(g_h0[i]);
}

// ---------------- fp32 SGEMM (h0 only) ----------------
template<int BM, int BN, int BK, int TM, int TN>
__global__ void __launch_bounds__(256)
sgemm_k(const float* __restrict__ A, int lda,
        const float* __restrict__ B, int ldb,
        float* __restrict__ C, int ldc,
        const float* __restrict__ bias, int K)
{
    constexpr int THREADS = (BM / TM) * (BN / TN);
    constexpr int ALOAD = BM * BK / THREADS;
    constexpr int BLOAD = BK * BN / THREADS;
    __shared__ float As[BK][BM + 1];
    __shared__ float Bs[BK][BN];
    const int tid = threadIdx.x;
    const int tx = tid % (BN / TN);
    const int ty = tid / (BN / TN);
    const int m0 = blockIdx.y * BM;
    const int n0 = blockIdx.x * BN;

    float acc[TM][TN];
#pragma unroll
    for (int i = 0; i < TM; i++)
#pragma unroll
        for (int j = 0; j < TN; j++) acc[i][j] = 0.f;

    for (int k0 = 0; k0 < K; k0 += BK) {
#pragma unroll
        for (int l = 0; l < ALOAD; l++) {
            int idx = tid + l * THREADS;
            int k = idx % BK, m = idx / BK;
            As[k][m] = A[(size_t)(m0 + m) * lda + k0 + k];
        }
#pragma unroll
        for (int l = 0; l < BLOAD; l++) {
            int idx = tid + l * THREADS;
            int n = idx % BN, k = idx / BN;
            Bs[k][n] = B[(size_t)(k0 + k) * ldb + n0 + n];
        }
        __syncthreads();
#pragma unroll
        for (int kk = 0; kk < BK; kk++) {
            float a[TM], b[TN];
#pragma unroll
            for (int i = 0; i < TM; i++) a[i] = As[kk][ty * TM + i];
#pragma unroll
            for (int j = 0; j < TN; j++) b[j] = Bs[kk][tx * TN + j];
#pragma unroll
            for (int i = 0; i < TM; i++)
#pragma unroll
                for (int j = 0; j < TN; j++) acc[i][j] += a[i] * b[j];
        }
        __syncthreads();
    }
#pragma unroll
    for (int i = 0; i < TM; i++)
#pragma unroll
        for (int j = 0; j < TN; j++) {
            int n = n0 + tx * TN + j;
            C[(size_t)(m0 + ty * TM + i) * ldc + n] = acc[i][j] + bias[n];
        }
}

// ---------------- XWx bf16 MMA: [4096 x 2048] = g_xg @ g_WxiT^T + bi -------
__global__ void __launch_bounds__(256)
xwx_mma_kernel() {
    __shared__ __align__(16) __nv_bfloat16 As[2][128][40];
    __shared__ __align__(16) __nv_bfloat16 Bs[2][128][40];
    int tid = threadIdx.x;
    int lane = tid & 31, wid = tid >> 5;
    int wm = wid & 1, wn = wid >> 1;     // warp tile 64m x 32n
    int m0 = blockIdx.x * 128;           // 32
    int n0 = blockIdx.y * 128;           // 16

    float acc[4][4][4];
#pragma unroll
    for (int a = 0; a < 4; a++)
#pragma unroll
        for (int b = 0; b < 4; b++)
#pragma unroll
            for (int c = 0; c < 4; c++) acc[a][b][c] = 0.f;

    auto loadA = [&](int s, int k0) {
#pragma unroll
        for (int l = 0; l < 2; l++) {
            int idx = tid + l * 256;
            int row = idx >> 2, ch = idx & 3;
            cp16(&As[s][row][ch * 8], g_xg + (size_t)(m0 + row) * WD + k0 + ch * 8);
        }
    };
    auto loadB = [&](int s, int k0) {
#pragma unroll
        for (int l = 0; l < 2; l++) {
            int idx = tid + l * 256;
            int row = idx >> 2, ch = idx & 3;
            cp16(&Bs[s][row][ch * 8], g_WxiT + (size_t)(n0 + row) * WD + k0 + ch * 8);
        }
    };
    loadA(0, 0); loadB(0, 0); cp_commit();

    constexpr int NIT = WD / 32;  // 8
    for (int it = 0; it < NIT; it++) {
        if (it + 1 < NIT) {
            int s = (it + 1) & 1;
            loadA(s, (it + 1) * 32); loadB(s, (it + 1) * 32);
            cp_commit(); cp_wait<1>();
        } else cp_wait<0>();
        __syncthreads();
        int s = it & 1;
        uint32_t aBase = smem_u32(&As[s][0][0]);
        uint32_t bBase = smem_u32(&Bs[s][0][0]);
#pragma unroll
        for (int ks = 0; ks < 2; ks++) {
            uint32_t a[4][4], b[4][2];
#pragma unroll
            for (int mf = 0; mf < 4; mf++) {
                int row = wm * 64 + mf * 16 + (lane & 15);
                ldsm4(a[mf][0], a[mf][1], a[mf][2], a[mf][3],
                      aBase + row * 80 + (ks * 16 + (lane >> 4) * 8) * 2);
            }
#pragma unroll
            for (int nf = 0; nf < 4; nf++) {
                int row = wn * 32 + nf * 8 + (lane & 7);
                ldsm2(b[nf][0], b[nf][1],
                      bBase + row * 80 + (ks * 16 + ((lane >> 3) & 1) * 8) * 2);
            }
#pragma unroll
            for (int mf = 0; mf < 4; mf++)
#pragma unroll
                for (int nf = 0; nf < 4; nf++)
                    mma16816(acc[mf][nf], a[mf], b[nf]);
        }
        __syncthreads();
    }

#pragma unroll
    for (int mf = 0; mf < 4; mf++) {
        int r = m0 + wm * 64 + mf * 16 + (lane >> 2);
#pragma unroll
        for (int nf = 0; nf < 4; nf++) {
            int c = n0 + wn * 32 + nf * 8 + 2 * (lane & 3);
            float b0 = g_bi[c], b1 = g_bi[c + 1];
            float2 v0 = {acc[mf][nf][0] + b0, acc[mf][nf][1] + b1};
            float2 v1 = {acc[mf][nf][2] + b0, acc[mf][nf][3] + b1};
            *(float2*)&g_XWx[(size_t)r * G4 + c] = v0;
            *(float2*)&g_XWx[(size_t)(r + 8) * G4 + c] = v1;
        }
    }
}

// ---------------- LSTM step: bf16 MMA (128x32x512) + fused gates -----------
__global__ void __launch_bounds__(256)
lstm_mma_step(const __nv_bfloat16* __restrict__ Aptr, int rowStride, int t) {
    __shared__ __align__(16) __nv_bfloat16 As[2][128][40];
    __shared__ __align__(16) __nv_bfloat16 Bs[2][32][40];
    int tid = threadIdx.x;
    int lane = tid & 31, wid = tid >> 5;
    int wm = wid >> 2, wn = wid & 3;     // warp tile 64m x 8n
    int n0 = blockIdx.x * 32;            // 64 blocks

    float acc[4][4];
#pragma unroll
    for (int a = 0; a < 4; a++)
#pragma unroll
        for (int c = 0; c < 4; c++) acc[a][c] = 0.f;

    auto loadA = [&](int s, int k0) {
#pragma unroll
        for (int l = 0; l < 2; l++) {
            int idx = tid + l * 256;
            int row = idx >> 2, ch = idx & 3;
            cp16(&As[s][row][ch * 8], Aptr + (size_t)row * rowStride + k0 + ch * 8);
        }
    };
    auto loadB = [&](int s, int k0) {
        if (tid < 128) {
            int row = tid >> 2, ch = tid & 3;
            cp16(&Bs[s][row][ch * 8], g_WhiT + (size_t)(n0 + row) * HH + k0 + ch * 8);
        }
    };
    loadA(0, 0); loadB(0, 0); cp_commit();

    constexpr int NIT = HH / 32;  // 16
    for (int it = 0; it < NIT; it++) {
        if (it + 1 < NIT) {
            int s = (it + 1) & 1;
            loadA(s, (it + 1) * 32); loadB(s, (it + 1) * 32);
            cp_commit(); cp_wait<1>();
        } else cp_wait<0>();
        __syncthreads();
        int s = it & 1;
        uint32_t aBase = smem_u32(&As[s][0][0]);
        uint32_t bBase = smem_u32(&Bs[s][0][0]);
#pragma unroll
        for (int ks = 0; ks < 2; ks++) {
            uint32_t a[4][4], b[2];
#pragma unroll
            for (int mf = 0; mf < 4; mf++) {
                int row = wm * 64 + mf * 16 + (lane & 15);
                ldsm4(a[mf][0], a[mf][1], a[mf][2], a[mf][3],
                      aBase + row * 80 + (ks * 16 + (lane >> 4) * 8) * 2);
            }
            {
                int row = wn * 8 + (lane & 7);
                ldsm2(b[0], b[1],
                      bBase + row * 80 + (ks * 16 + ((lane >> 3) & 1) * 8) * 2);
            }
#pragma unroll
            for (int mf = 0; mf < 4; mf++)
                mma16816(acc[mf], a[mf], b);
        }
        __syncthreads();
    }

    // fused gate epilogue (gate-interleaved cols: c%4 -> 0:i 1:f 2:o 3:g)
    int cbase = n0 + wn * 8 + 2 * (lane & 3);
    int j = cbase >> 2;
#pragma unroll
    for (int mf = 0; mf < 4; mf++) {
        int r = wm * 64 + mf * 16 + (lane >> 2);
        float2 x0 = *(const float2*)&g_XWx[(size_t)((r << 5) + t) * G4 + cbase];
        float2 x1 = *(const float2*)&g_XWx[(size_t)(((r + 8) << 5) + t) * G4 + cbase];
        float v0 = acc[mf][0] + x0.x, v1 = acc[mf][1] + x0.y;
        float v2 = acc[mf][2] + x1.x, v3 = acc[mf][3] + x1.y;
        float e0 = __shfl_xor_sync(0xffffffffu, v0, 1);
        float e1 = __shfl_xor_sync(0xffffffffu, v1, 1);
        float e2 = __shfl_xor_sync(0xffffffffu, v2, 1);
        float e3 = __shfl_xor_sync(0xffffffffu, v3, 1);
        if (!(lane & 1)) {
            {
                float i_ = sigmoidf_(v0), f_ = sigmoidf_(v1);
                float o_ = sigmoidf_(e0), gg = tanhf(e1);
                float cp = t ? g_c[r * HH + j] : 0.f;
                float cn = f_ * cp + i_ * gg;
                g_c[r * HH + j] = cn;
                g_hb[(size_t)((r << 5) + t) * HH + j] = __float2bfloat16(o_ * tanhf(cn));
            }
            {
                int r8 = r + 8;
                float i_ = sigmoidf_(v2), f_ = sigmoidf_(v3);
                float o_ = sigmoidf_(e2), gg = tanhf(e3);
                float cp = t ? g_c[r8 * HH + j] : 0.f;
                float cn = f_ * cp + i_ * gg;
                g_c[r8 * HH + j] = cn;
                g_hb[(size_t)((r8 << 5) + t) * HH + j] = __float2bfloat16(o_ * tanhf(cn));
            }
        }
    }
}

// ---------------- vocab bf16 MMA GEMM + fused sum-exp epilogue --------------
__global__ void __launch_bounds__(256)
vocab_mma_kernel(const float* __restrict__ bv) {
    __shared__ __align__(16) __nv_bfloat16 As[2][VBM][40];
    __shared__ __align__(16) __nv_bfloat16 Bs[2][VBN][40];
    __shared__ float sred[4][VBM];
    int tid = threadIdx.x;
    int lane = tid & 31, wid = tid >> 5;
    int wm = wid & 1, wn = wid >> 1;
    int m0 = blockIdx.x * VBM;
    int n0 = blockIdx.y * VBN;

    float acc[4][4][4];
#pragma unroll
    for (int a = 0; a < 4; a++)
#pragma unroll
        for (int b = 0; b < 4; b++)
#pragma unroll
            for (int c = 0; c < 4; c++) acc[a][b][c] = 0.f;

    auto loadA = [&](int s, int k0) {
#pragma unroll
        for (int l = 0; l < 2; l++) {
            int idx = tid + l * 256;
            int row = idx >> 2, ch = idx & 3;
            cp16(&As[s][row][ch * 8], g_hb + (size_t)(m0 + row) * HH + k0 + ch * 8);
        }
    };
    auto loadB = [&](int s, int k0) {
#pragma unroll
        for (int l = 0; l < 2; l++) {
            int idx = tid + l * 256;
            int row = idx >> 2, ch = idx & 3;
            cp16(&Bs[s][row][ch * 8], g_wt + (size_t)(n0 + row) * HH + k0 + ch * 8);
        }
    };
    loadA(0, 0); loadB(0, 0); cp_commit();

    constexpr int NIT = HH / VBK;  // 16
    for (int it = 0; it < NIT; it++) {
        if (it + 1 < NIT) {
            int s = (it + 1) & 1;
            loadA(s, (it + 1) * VBK); loadB(s, (it + 1) * VBK);
            cp_commit(); cp_wait<1>();
        } else cp_wait<0>();
        __syncthreads();
        int s = it & 1;
        uint32_t aBase = smem_u32(&As[s][0][0]);
        uint32_t bBase = smem_u32(&Bs[s][0][0]);
#pragma unroll
        for (int ks = 0; ks < 2; ks++) {
            uint32_t a[4][4], b[4][2];
#pragma unroll
            for (int mf = 0; mf < 4; mf++) {
                int row = wm * 64 + mf * 16 + (lane & 15);
                ldsm4(a[mf][0], a[mf][1], a[mf][2], a[mf][3],
                      aBase + row * 80 + (ks * 16 + (lane >> 4) * 8) * 2);
            }
#pragma unroll
            for (int nf = 0; nf < 4; nf++) {
                int row = wn * 32 + nf * 8 + (lane & 7);
                ldsm2(b[nf][0], b[nf][1],
                      bBase + row * 80 + (ks * 16 + ((lane >> 3) & 1) * 8) * 2);
            }
#pragma unroll
            for (int mf = 0; mf < 4; mf++)
#pragma unroll
                for (int nf = 0; nf < 4; nf++)
                    mma16816(acc[mf][nf], a[mf], b[nf]);
        }
        __syncthreads();
    }

    float rowsum[4][2] = {};
#pragma unroll
    for (int nf = 0; nf < 4; nf++) {
        int nb_ = n0 + wn * 32 + nf * 8 + 2 * (lane & 3);
        float b0 = bv[nb_], b1 = bv[nb_ + 1];
#pragma unroll
        for (int mf = 0; mf < 4; mf++) {
            rowsum[mf][0] += __expf(acc[mf][nf][0] + b0) + __expf(acc[mf][nf][1] + b1);
            rowsum[mf][1] += __expf(acc[mf][nf][2] + b0) + __expf(acc[mf][nf][3] + b1);
        }
    }
#pragma unroll
    for (int mf = 0; mf < 4; mf++)
#pragma unroll
        for (int h = 0; h < 2; h++) {
            rowsum[mf][h] += __shfl_xor_sync(0xffffffffu, rowsum[mf][h], 1);
            rowsum[mf][h] += __shfl_xor_sync(0xffffffffu, rowsum[mf][h], 2);
        }
    if ((lane & 3) == 0) {
#pragma unroll
        for (int mf = 0; mf < 4; mf++) {
            int r = wm * 64 + mf * 16 + (lane >> 2);
            sred[wn][r]     = rowsum[mf][0];
            sred[wn][r + 8] = rowsum[mf][1];
        }
    }
    __syncthreads();
    if (tid < VBM) {
        float s = sred[0][tid] + sred[1][tid] + sred[2][tid] + sred[3][tid];
        g_part[(size_t)(m0 + tid) * NTILES_V + blockIdx.y] = s;
    }
}

// ---------------- target scores (coalesced bf16) ----------------
__global__ void tscore_kernel(const float* __restrict__ bv) {
    int w = (blockIdx.x * blockDim.x + threadIdx.x) >> 5;
    int lane = threadIdx.x & 31;
    if (w >= M_NT) return;
    int tgt = g_tgt[w];
    const uint4* h4 = (const uint4*)(g_hb + (size_t)w * HH);
    const uint4* w4 = (const uint4*)(g_wt + (size_t)tgt * HH);
    float s = 0.f;
#pragma unroll
    for (int i = 0; i < 2; i++) {
        uint4 a = h4[lane + i * 32];
        uint4 b = w4[lane + i * 32];
        const uint32_t* ap = &a.x;
        const uint32_t* bp = &b.x;
#pragma unroll
        for (int q = 0; q < 4; q++) {
            float2 fa = __bfloat1622float2(*(const __nv_bfloat162*)&ap[q]);
            float2 fb = __bfloat1622float2(*(const __nv_bfloat162*)&bp[q]);
            s += fa.x * fb.x + fa.y * fb.y;
        }
    }
#pragma unroll
    for (int off = 16; off; off >>= 1) s += __shfl_down_sync(0xffffffffu, s, off);
    if (lane == 0) g_tsc[w] = s + bv[tgt];
}

// ---------------- per-token nll + final loss ----------------
__global__ void nll_kernel() {
    int w = (blockIdx.x * blockDim.x + threadIdx.x) >> 5;
    int lane = threadIdx.x & 31;
    if (w >= M_NT) return;
    const float* p = g_part + (size_t)w * NTILES_V;
    float s = 0.f;
    for (int i = lane; i < NTILES_V; i += 32) s += p[i];
#pragma unroll
    for (int off = 16; off; off >>= 1) s += __shfl_down_sync(0xffffffffu, s, off);
    if (lane == 0)
        g_nll[w] = (g_tgt[w] != 0) ? (logf(s) - g_tsc[w]) : 0.f;
}

__global__ void loss_kernel(float* __restrict__ out) {
    __shared__ float sm[256];
    float s = 0.f;
    for (int i = threadIdx.x; i < M_NT; i += 256) s += g_nll[i];
    sm[threadIdx.x] = s;
    __syncthreads();
    for (int off = 128; off; off >>= 1) {
        if (threadIdx.x < off) sm[threadIdx.x] += sm[threadIdx.x + off];
        __syncthreads();
    }
    if (threadIdx.x == 0) out[0] = sm[0] / (float)NB;
}

// ---------------- launch ----------------
extern "C" void kernel_launch(void* const* d_in, const int* in_sizes, int n_in,
                              void* d_out, int out_size) {
    const float* features = (const float*)d_in[0];
    const void*  captions =               d_in[1];
    const float* W_proj   = (const float*)d_in[2];
    const float* b_proj   = (const float*)d_in[3];
    const float* W_embed  = (const float*)d_in[4];
    const float* Wx       = (const float*)d_in[5];
    const float* Wh       = (const float*)d_in[6];
    const float* bb       = (const float*)d_in[7];
    const float* W_vocab  = (const float*)d_in[8];
    const float* b_vocab  = (const float*)d_in[9];
    float* out = (float*)d_out;

    float *p_h0, *p_bi;
    __nv_bfloat16 *p_WxiT, *p_WhiT, *p_h0b, *p_hb;
    cudaGetSymbolAddress((void**)&p_h0,   g_h0);
    cudaGetSymbolAddress((void**)&p_bi,   g_bi);
    cudaGetSymbolAddress((void**)&p_WxiT, g_WxiT);
    cudaGetSymbolAddress((void**)&p_WhiT, g_WhiT);
    cudaGetSymbolAddress((void**)&p_h0b,  g_h0b);
    cudaGetSymbolAddress((void**)&p_hb,   g_hb);

    // 0. indices + weight conversions
    detect_kernel<<<1, 256>>>((const unsigned int*)captions);
    build_idx_kernel<<<(M_NT + 255) / 256, 256>>>(captions);
    reorder_bias_kernel<<<(G4 + 255) / 256, 256>>>(bb, p_bi);
    transT_gate_kernel<<<dim3(G4 / 32, WD / 32), dim3(32, 8)>>>(Wx, p_WxiT, WD);
    transT_gate_kernel<<<dim3(G4 / 32, HH / 32), dim3(32, 8)>>>(Wh, p_WhiT, HH);
    convW_kernel<<<dim3(VV / 32, HH / 32), dim3(32, 8)>>>(W_vocab);
    gatherconv_kernel<<<(M_NT * WD + 255) / 256, 256>>>(W_embed);

    // 1. h0 = features @ W_proj + b_proj (fp32), then bf16
    sgemm_k<32, 64, 16, 2, 4><<<dim3(HH / 64, NB / 32), 256>>>(
        features, DF, W_proj, HH, p_h0, HH, b_proj, DF);
    convh0_kernel<<<(NB * HH + 255) / 256, 256>>>();

    // 2. XWx = gathered embeds @ WxiT^T + bi (bf16 MMA)
    xwx_mma_kernel<<<dim3(M_NT / 128, G4 / 128), 256>>>();

    // 3. LSTM: 32 serial bf16-MMA steps with fused gates
    for (int t = 0; t < TT; t++) {
        const __nv_bfloat16* Aptr = (t == 0) ? p_h0b : (p_hb + (size_t)(t - 1) * HH);
        int stride = (t == 0) ? HH : (TT * HH);
        lstm_mma_step<<<G4 / 32, 256>>>(Aptr, stride, t);
    }

    // 4. vocab bf16 MMA GEMM + fused sum-exp
    vocab_mma_kernel<<<dim3(M_NT / VBM, NTILES_V), 256>>>(b_vocab);

    // 5. target scores, per-token nll, final loss
    tscore_kernel<<<M_NT / 4, 128>>>(b_vocab);
    nll_kernel<<<M_NT / 4, 128>>>();
    loss_kernel<<<1, 256>>>(out);
}